// round 15
// baseline (speedup 1.0000x reference)
#include <cuda_runtime.h>
#include <cuda_fp16.h>
#include <math.h>
#include <stdint.h>

#define Bc 4
#define Tc 256
#define Uc 128
#define Ec 512
#define Dc 640
#define Hc 512
#define Vc 640

// Scratch (no cudaMalloc allowed).
__device__ float g_enc[Bc * Tc * Hc];    // [B*T, H]
__device__ float g_dec[Bc * Uc * Hc];    // [B*U, H]
// W_out pre-packed into mma.sync B-fragment layout:
// g_Wf[(nt*32 + kt)*32 + lane] = {pack(W[kt*16+2*(l%4)][nt*8+l/4], W[..+1][..]),
//                                 pack(W[kt*16+2*(l%4)+8][..],    W[..+9][..])}
__device__ uint2 g_Wf[80 * 32 * 32];     // 640KB

// ---------------------------------------------------------------------------
// Helpers (sm_80-era PTX only — no 'a'-gated instructions)
// ---------------------------------------------------------------------------
__device__ __forceinline__ uint32_t smem_u32(const void* p) {
    return (uint32_t)__cvta_generic_to_shared(p);
}
__device__ __forceinline__ void ldmx4(uint32_t* r, uint32_t addr) {
    asm volatile("ldmatrix.sync.aligned.m8n8.x4.shared.b16 {%0,%1,%2,%3}, [%4];"
                 : "=r"(r[0]), "=r"(r[1]), "=r"(r[2]), "=r"(r[3]) : "r"(addr));
}
__device__ __forceinline__ void mma16816(float* d, const uint32_t* a,
                                         uint32_t b0, uint32_t b1) {
    asm volatile(
        "mma.sync.aligned.m16n8k16.row.col.f32.f16.f16.f32 "
        "{%0,%1,%2,%3}, {%4,%5,%6,%7}, {%8,%9}, {%0,%1,%2,%3};"
        : "+f"(d[0]), "+f"(d[1]), "+f"(d[2]), "+f"(d[3])
        : "r"(a[0]), "r"(a[1]), "r"(a[2]), "r"(a[3]), "r"(b0), "r"(b1));
}
__device__ __forceinline__ float tanh_fast(float x) {
    asm("tanh.approx.f32 %0, %0;" : "+f"(x));
    return x;
}
__device__ __forceinline__ uint32_t pack2(float a, float b) {
    __half2 h = __floats2half2_rn(a, b);
    return *reinterpret_cast<uint32_t*>(&h);
}
__device__ __forceinline__ uint32_t pack2h(__half a, __half b) {
    __half2 h = __halves2half2(a, b);
    return *reinterpret_cast<uint32_t*>(&h);
}

// ---------------------------------------------------------------------------
// Prep kernel: z=0 enc proj, z=1 dec proj, z=2 W-fragment builder.
// Proj: 64x64 tile, BK=32.
// ---------------------------------------------------------------------------
__global__ __launch_bounds__(256, 2) void prep_kernel(
    const float* __restrict__ enc_out, const float* __restrict__ dec_out,
    const float* __restrict__ W_enc, const float* __restrict__ b_enc,
    const float* __restrict__ W_dec, const float* __restrict__ W_out)
{
    int z = blockIdx.z;
    int tid = threadIdx.x;

    __shared__ float As[32][64];
    __shared__ float Ws[32][64];

    if (z == 2) {   // build g_Wf for ntile nt (8 v-columns, full K)
        __shared__ __half hbuf[512][8];
        int nt = blockIdx.y * 8 + blockIdx.x;
        if (nt >= 80) return;
        #pragma unroll
        for (int i = 0; i < 4; i++) {
            int row = i * 128 + (tid >> 1);
            int c4 = (tid & 1) * 4;
            float4 v = *(const float4*)&W_out[(size_t)row * Vc + nt * 8 + c4];
            hbuf[row][c4 + 0] = __float2half_rn(v.x);
            hbuf[row][c4 + 1] = __float2half_rn(v.y);
            hbuf[row][c4 + 2] = __float2half_rn(v.z);
            hbuf[row][c4 + 3] = __float2half_rn(v.w);
        }
        __syncthreads();
        #pragma unroll
        for (int j = 0; j < 4; j++) {
            int idx = j * 256 + tid;
            int kt = idx >> 5, l = idx & 31;
            int n = l >> 2, k0 = kt * 16 + (l & 3) * 2;
            uint2 q;
            q.x = pack2h(hbuf[k0][n], hbuf[k0 + 1][n]);
            q.y = pack2h(hbuf[k0 + 8][n], hbuf[k0 + 9][n]);
            g_Wf[(nt * 32 + kt) * 32 + l] = q;
        }
        return;
    }

    const float* A; const float* W; const float* bias; float* C; int K;
    if (z == 0) {
        A = enc_out; W = W_enc; bias = b_enc; K = Ec;
        float* p; asm("cvta.global.u64 %0, g_enc;" : "=l"(p)); C = p;
    } else {
        if (blockIdx.y >= 8) return;
        A = dec_out; W = W_dec; bias = nullptr; K = Dc;
        float* p; asm("cvta.global.u64 %0, g_dec;" : "=l"(p)); C = p;
    }
    const int N = Hc;

    int row0 = blockIdx.y * 64, col0 = blockIdx.x * 64;
    int tx = tid & 15, ty = tid >> 4;
    float acc[4][4] = {};

    int rA = tid >> 2, kqA = (tid & 3) * 4;
    int kW = tid >> 4, cqW = (tid & 15) * 4;

    float4 a0 = *(const float4*)&A[(size_t)(row0 + rA) * K + kqA];
    float4 a1 = *(const float4*)&A[(size_t)(row0 + rA) * K + kqA + 16];
    float4 w0 = *(const float4*)&W[(size_t)kW * N + col0 + cqW];
    float4 w1 = *(const float4*)&W[(size_t)(kW + 16) * N + col0 + cqW];

    const int NK = K / 32;
    for (int kt = 0; kt < NK; kt++) {
        __syncthreads();
        As[kqA + 0][rA] = a0.x; As[kqA + 1][rA] = a0.y;
        As[kqA + 2][rA] = a0.z; As[kqA + 3][rA] = a0.w;
        As[kqA + 16][rA] = a1.x; As[kqA + 17][rA] = a1.y;
        As[kqA + 18][rA] = a1.z; As[kqA + 19][rA] = a1.w;
        *(float4*)&Ws[kW][cqW] = w0;
        *(float4*)&Ws[kW + 16][cqW] = w1;
        __syncthreads();
        if (kt + 1 < NK) {
            int k0 = (kt + 1) * 32;
            a0 = *(const float4*)&A[(size_t)(row0 + rA) * K + k0 + kqA];
            a1 = *(const float4*)&A[(size_t)(row0 + rA) * K + k0 + kqA + 16];
            w0 = *(const float4*)&W[(size_t)(k0 + kW) * N + col0 + cqW];
            w1 = *(const float4*)&W[(size_t)(k0 + kW + 16) * N + col0 + cqW];
        }
        #pragma unroll
        for (int kk = 0; kk < 32; kk++) {
            float a[4], b[4];
            #pragma unroll
            for (int i = 0; i < 4; i++) a[i] = As[kk][ty * 4 + i];
            #pragma unroll
            for (int j = 0; j < 4; j++) b[j] = Ws[kk][tx * 4 + j];
            #pragma unroll
            for (int i = 0; i < 4; i++)
                #pragma unroll
                for (int j = 0; j < 4; j++)
                    acc[i][j] += a[i] * b[j];
        }
    }
    #pragma unroll
    for (int i = 0; i < 4; i++) {
        int r = row0 + ty * 4 + i;
        #pragma unroll
        for (int j = 0; j < 4; j++) {
            int c = col0 + tx * 4 + j;
            float v = acc[i][j];
            if (bias) v += bias[c];
            C[(size_t)r * N + c] = v;
        }
    }
}

// ---------------------------------------------------------------------------
// Fused joint kernel v8: CTA = (bt, u-half), 2048 CTAs, 1 CTA/SM, ~200 regs.
//   A[64u x 512k] fp16(tanh.approx(enc+dec)) resident in SMEM (64KB),
//   filled up-front; ONE __syncthreads, then zero barriers.
//   Warp tile 64x64 (4mf x 8nf): bytes/MMA = 512/8 + 256/4 = 128B = 1 wf/MMA
//   (vs 192B/1.5wf at 64x32) — lifts the L1tex wavefront ceiling on the
//   tensor pipe from ~67% to ~100%.
//   B frags: 3-slot rolling distance-2 LDG prefetch (r13-proven).
//   vt0: v in [0,512) (n0 = w*64, NF=8). vt1: v in [512,640) (NF=2).
// ---------------------------------------------------------------------------
#define JSMEM 65536                 // A only

template<int NF>
__device__ __forceinline__ void run_vt(
    uint32_t sbA, const uint2* __restrict__ wbase,
    const float* __restrict__ bout, float* __restrict__ outbt,
    int vtn0, int rowA, uint32_t swz, int khA, int l)
{
    int gr = l >> 2, ct = l & 3;
    float acc[4][NF][4];
    #pragma unroll
    for (int nf = 0; nf < NF; nf++) {
        int cc = vtn0 + nf * 8 + 2 * ct;
        float b0 = __ldg(&bout[cc]), b1 = __ldg(&bout[cc + 1]);
        #pragma unroll
        for (int mf = 0; mf < 4; mf++) {
            acc[mf][nf][0] = b0; acc[mf][nf][1] = b1;
            acc[mf][nf][2] = b0; acc[mf][nf][3] = b1;
        }
    }

    uint2 bf[3][NF];
    #pragma unroll
    for (int p = 0; p < 2; p++)
        #pragma unroll
        for (int nb = 0; nb < NF; nb++)
            bf[p][nb] = __ldg(wbase + nb * 1024 + p * 32);

    // One ks iteration; cur = ks%3 (compile-time). Prefetch for ks+2 is
    // issued FIRST (into the slot freed at ks-1) → ~2 iterations of cover.
    #define KS_ITER(ks, cur)                                                  \
    do {                                                                      \
        if ((ks) + 2 < 32) {                                                  \
            _Pragma("unroll")                                                 \
            for (int nb = 0; nb < NF; nb++)                                   \
                bf[((cur) + 2) % 3][nb] =                                     \
                    __ldg(wbase + nb * 1024 + ((ks) + 2) * 32);               \
        }                                                                     \
        uint32_t bc = (uint32_t)((ks) * 32 + khA) ^ swz;                      \
        uint32_t a[2][4];                                                     \
        _Pragma("unroll")                                                     \
        for (int mf = 0; mf < 2; mf++)                                        \
            ldmx4(a[mf], sbA + (uint32_t)(mf * 16 + rowA) * 1024 + bc);       \
        _Pragma("unroll")                                                     \
        for (int mf = 0; mf < 2; mf++)                                        \
            _Pragma("unroll")                                                 \
            for (int nf = 0; nf < NF; nf++)                                   \
                mma16816(acc[mf][nf], a[mf], bf[cur][nf].x, bf[cur][nf].y);   \
        _Pragma("unroll")                                                     \
        for (int mf = 0; mf < 2; mf++)                                        \
            ldmx4(a[mf], sbA + (uint32_t)((mf + 2) * 16 + rowA) * 1024 + bc); \
        _Pragma("unroll")                                                     \
        for (int mf = 0; mf < 2; mf++)                                        \
            _Pragma("unroll")                                                 \
            for (int nf = 0; nf < NF; nf++)                                   \
                mma16816(acc[mf + 2][nf], a[mf], bf[cur][nf].x, bf[cur][nf].y); \
    } while (0)

    for (int ks = 0; ks < 30; ks += 3) {
        KS_ITER(ks, 0);
        KS_ITER(ks + 1, 1);
        KS_ITER(ks + 2, 2);
    }
    KS_ITER(30, 0);
    KS_ITER(31, 1);
    #undef KS_ITER

    // Epilogue (bias already folded in).
    #pragma unroll
    for (int nf = 0; nf < NF; nf++) {
        int cc = vtn0 + nf * 8 + 2 * ct;
        #pragma unroll
        for (int mf = 0; mf < 4; mf++) {
            int u = mf * 16 + gr;
            float* p = outbt + (size_t)u * Vc + cc;
            float2 t0; t0.x = acc[mf][nf][0]; t0.y = acc[mf][nf][1];
            float2 t1; t1.x = acc[mf][nf][2]; t1.y = acc[mf][nf][3];
            *(float2*)p = t0;
            *(float2*)(p + 8 * Vc) = t1;
        }
    }
}

__global__ __launch_bounds__(256) void joint_kernel(
    const float* __restrict__ bout, float* __restrict__ out)
{
    extern __shared__ char smem[];
    uint32_t sbA = smem_u32(smem);
    int tid = threadIdx.x, l = tid & 31, w = tid >> 5;
    int bx = blockIdx.x;
    int bt = bx >> 1, uh = bx & 1;
    int b = bt >> 8;
    const float* encR = g_enc + (size_t)bt * Hc;
    const float* decB = g_dec + ((size_t)b * Uc + uh * 64) * Hc;

    // Fill A[64][512]: rows have 1024B stride, SW128-style XOR swizzle.
    #pragma unroll
    for (int i = 0; i < 16; i++) {
        int idx = i * 256 + tid;          // 4096 units of 8 halfs
        int r = idx >> 6, cg = idx & 63;
        int kc = cg * 8;
        float4 d0 = *(const float4*)(decB + (size_t)r * Hc + kc);
        float4 d1 = *(const float4*)(decB + (size_t)r * Hc + kc + 4);
        float4 e0 = *(const float4*)(encR + kc);
        float4 e1 = *(const float4*)(encR + kc + 4);
        uint4 q;
        q.x = pack2(tanh_fast(d0.x + e0.x), tanh_fast(d0.y + e0.y));
        q.y = pack2(tanh_fast(d0.z + e0.z), tanh_fast(d0.w + e0.w));
        q.z = pack2(tanh_fast(d1.x + e1.x), tanh_fast(d1.y + e1.y));
        q.w = pack2(tanh_fast(d1.z + e1.z), tanh_fast(d1.w + e1.w));
        uint32_t off = (uint32_t)r * 1024 + (((uint32_t)cg * 16) ^ (((uint32_t)r & 7) << 4));
        asm volatile("st.shared.v4.b32 [%0], {%1,%2,%3,%4};"
                     :: "r"(sbA + off), "r"(q.x), "r"(q.y), "r"(q.z), "r"(q.w)
                     : "memory");
    }
    __syncthreads();   // the ONLY barrier

    int rowA = l & 15, khA = (l >> 4) * 16;
    uint32_t swz = ((uint32_t)l & 7) << 4;
    float* outbt = out + ((size_t)bt * Uc + uh * 64) * Vc;

    {
        int n0 = w * 64;                                    // NF=8: v [0,512)
        const uint2* wb = g_Wf + (size_t)(n0 >> 3) * 1024 + l;
        run_vt<8>(sbA, wb, bout, outbt, n0, rowA, swz, khA, l);
    }
    {
        int n0 = 512 + w * 16;                              // NF=2: v [512,640)
        const uint2* wb = g_Wf + (size_t)(n0 >> 3) * 1024 + l;
        run_vt<2>(sbA, wb, bout, outbt, n0, rowA, swz, khA, l);
    }
}

// ---------------------------------------------------------------------------
extern "C" void kernel_launch(void* const* d_in, const int* in_sizes, int n_in,
                              void* d_out, int out_size)
{
    const float* enc_out = (const float*)d_in[0];
    const float* dec_out = (const float*)d_in[1];
    const float* W_enc   = (const float*)d_in[2];
    const float* b_enc   = (const float*)d_in[3];
    const float* W_dec   = (const float*)d_in[4];
    const float* W_out   = (const float*)d_in[5];
    const float* b_out   = (const float*)d_in[6];
    float* out = (float*)d_out;

    cudaFuncSetAttribute(joint_kernel,
                         cudaFuncAttributeMaxDynamicSharedMemorySize, JSMEM);

    prep_kernel<<<dim3(8, 16, 3), 256>>>(enc_out, dec_out, W_enc, b_enc, W_dec, W_out);
    joint_kernel<<<2 * Bc * Tc, 256, JSMEM>>>(b_out, out);
}

// round 16
// speedup vs baseline: 1.0964x; 1.0964x over previous
#include <cuda_runtime.h>
#include <cuda_fp16.h>
#include <math.h>
#include <stdint.h>

#define Bc 4
#define Tc 256
#define Uc 128
#define Ec 512
#define Dc 640
#define Hc 512
#define Vc 640

// Scratch (no cudaMalloc allowed).
__device__ float g_enc[Bc * Tc * Hc];    // [B*T, H]
__device__ float g_dec[Bc * Uc * Hc];    // [B*U, H]
// W_out pre-packed into mma.sync B-fragment layout:
// g_Wf[(nt*32 + kt)*32 + lane] = {pack(W[kt*16+2*(l%4)][nt*8+l/4], W[..+1][..]),
//                                 pack(W[kt*16+2*(l%4)+8][..],    W[..+9][..])}
__device__ uint2 g_Wf[80 * 32 * 32];     // 640KB

// ---------------------------------------------------------------------------
// Helpers (sm_80-era PTX only — no 'a'-gated instructions)
// ---------------------------------------------------------------------------
__device__ __forceinline__ uint32_t smem_u32(const void* p) {
    return (uint32_t)__cvta_generic_to_shared(p);
}
__device__ __forceinline__ void ldmx4(uint32_t* r, uint32_t addr) {
    asm volatile("ldmatrix.sync.aligned.m8n8.x4.shared.b16 {%0,%1,%2,%3}, [%4];"
                 : "=r"(r[0]), "=r"(r[1]), "=r"(r[2]), "=r"(r[3]) : "r"(addr));
}
__device__ __forceinline__ void mma16816(float* d, const uint32_t* a,
                                         uint32_t b0, uint32_t b1) {
    asm volatile(
        "mma.sync.aligned.m16n8k16.row.col.f32.f16.f16.f32 "
        "{%0,%1,%2,%3}, {%4,%5,%6,%7}, {%8,%9}, {%0,%1,%2,%3};"
        : "+f"(d[0]), "+f"(d[1]), "+f"(d[2]), "+f"(d[3])
        : "r"(a[0]), "r"(a[1]), "r"(a[2]), "r"(a[3]), "r"(b0), "r"(b1));
}
__device__ __forceinline__ float tanh_fast(float x) {
    asm("tanh.approx.f32 %0, %0;" : "+f"(x));
    return x;
}
__device__ __forceinline__ uint32_t pack2(float a, float b) {
    __half2 h = __floats2half2_rn(a, b);
    return *reinterpret_cast<uint32_t*>(&h);
}
__device__ __forceinline__ uint32_t pack2h(__half a, __half b) {
    __half2 h = __halves2half2(a, b);
    return *reinterpret_cast<uint32_t*>(&h);
}

// ---------------------------------------------------------------------------
// Prep kernel: z=0 enc proj, z=1 dec proj, z=2 W-fragment builder.
// Proj: 64x64 tile, BK=32.
// ---------------------------------------------------------------------------
__global__ __launch_bounds__(256, 2) void prep_kernel(
    const float* __restrict__ enc_out, const float* __restrict__ dec_out,
    const float* __restrict__ W_enc, const float* __restrict__ b_enc,
    const float* __restrict__ W_dec, const float* __restrict__ W_out)
{
    int z = blockIdx.z;
    int tid = threadIdx.x;

    __shared__ float As[32][64];
    __shared__ float Ws[32][64];

    if (z == 2) {   // build g_Wf for ntile nt (8 v-columns, full K)
        __shared__ __half hbuf[512][8];
        int nt = blockIdx.y * 8 + blockIdx.x;
        if (nt >= 80) return;
        #pragma unroll
        for (int i = 0; i < 4; i++) {
            int row = i * 128 + (tid >> 1);
            int c4 = (tid & 1) * 4;
            float4 v = *(const float4*)&W_out[(size_t)row * Vc + nt * 8 + c4];
            hbuf[row][c4 + 0] = __float2half_rn(v.x);
            hbuf[row][c4 + 1] = __float2half_rn(v.y);
            hbuf[row][c4 + 2] = __float2half_rn(v.z);
            hbuf[row][c4 + 3] = __float2half_rn(v.w);
        }
        __syncthreads();
        #pragma unroll
        for (int j = 0; j < 4; j++) {
            int idx = j * 256 + tid;
            int kt = idx >> 5, l = idx & 31;
            int n = l >> 2, k0 = kt * 16 + (l & 3) * 2;
            uint2 q;
            q.x = pack2h(hbuf[k0][n], hbuf[k0 + 1][n]);
            q.y = pack2h(hbuf[k0 + 8][n], hbuf[k0 + 9][n]);
            g_Wf[(nt * 32 + kt) * 32 + l] = q;
        }
        return;
    }

    const float* A; const float* W; const float* bias; float* C; int K;
    if (z == 0) {
        A = enc_out; W = W_enc; bias = b_enc; K = Ec;
        float* p; asm("cvta.global.u64 %0, g_enc;" : "=l"(p)); C = p;
    } else {
        if (blockIdx.y >= 8) return;
        A = dec_out; W = W_dec; bias = nullptr; K = Dc;
        float* p; asm("cvta.global.u64 %0, g_dec;" : "=l"(p)); C = p;
    }
    const int N = Hc;

    int row0 = blockIdx.y * 64, col0 = blockIdx.x * 64;
    int tx = tid & 15, ty = tid >> 4;
    float acc[4][4] = {};

    int rA = tid >> 2, kqA = (tid & 3) * 4;
    int kW = tid >> 4, cqW = (tid & 15) * 4;

    float4 a0 = *(const float4*)&A[(size_t)(row0 + rA) * K + kqA];
    float4 a1 = *(const float4*)&A[(size_t)(row0 + rA) * K + kqA + 16];
    float4 w0 = *(const float4*)&W[(size_t)kW * N + col0 + cqW];
    float4 w1 = *(const float4*)&W[(size_t)(kW + 16) * N + col0 + cqW];

    const int NK = K / 32;
    for (int kt = 0; kt < NK; kt++) {
        __syncthreads();
        As[kqA + 0][rA] = a0.x; As[kqA + 1][rA] = a0.y;
        As[kqA + 2][rA] = a0.z; As[kqA + 3][rA] = a0.w;
        As[kqA + 16][rA] = a1.x; As[kqA + 17][rA] = a1.y;
        As[kqA + 18][rA] = a1.z; As[kqA + 19][rA] = a1.w;
        *(float4*)&Ws[kW][cqW] = w0;
        *(float4*)&Ws[kW + 16][cqW] = w1;
        __syncthreads();
        if (kt + 1 < NK) {
            int k0 = (kt + 1) * 32;
            a0 = *(const float4*)&A[(size_t)(row0 + rA) * K + k0 + kqA];
            a1 = *(const float4*)&A[(size_t)(row0 + rA) * K + k0 + kqA + 16];
            w0 = *(const float4*)&W[(size_t)(k0 + kW) * N + col0 + cqW];
            w1 = *(const float4*)&W[(size_t)(k0 + kW + 16) * N + col0 + cqW];
        }
        #pragma unroll
        for (int kk = 0; kk < 32; kk++) {
            float a[4], b[4];
            #pragma unroll
            for (int i = 0; i < 4; i++) a[i] = As[kk][ty * 4 + i];
            #pragma unroll
            for (int j = 0; j < 4; j++) b[j] = Ws[kk][tx * 4 + j];
            #pragma unroll
            for (int i = 0; i < 4; i++)
                #pragma unroll
                for (int j = 0; j < 4; j++)
                    acc[i][j] += a[i] * b[j];
        }
    }
    #pragma unroll
    for (int i = 0; i < 4; i++) {
        int r = row0 + ty * 4 + i;
        #pragma unroll
        for (int j = 0; j < 4; j++) {
            int c = col0 + tx * 4 + j;
            float v = acc[i][j];
            if (bias) v += bias[c];
            C[(size_t)r * N + c] = v;
        }
    }
}

// ---------------------------------------------------------------------------
// Fused joint kernel v9: CTA = (bt, u-half), 2048 CTAs, 2 CTAs/SM.
//   A[64u x 512k] fp16(tanh.approx(enc+dec)) resident in SMEM (64KB),
//   filled up-front; ONE __syncthreads, then zero barriers.
//   Warp tile 64x40 (4mf x 5nf): wf/MMA = (16+5)/20 = 1.05 (vs 1.35 at
//   64x32/3-pass) — raises the L1tex-imposed tensor ceiling to ~95% while
//   keeping acc=80 regs → 2 CTAs/SM (16 warps, 4/SMSP, latency covered).
//   Each warp: contiguous 80 v-columns in TWO uniform passes of 40.
//   B frags: 2-slot ping-pong LDG (refill for ks+2 at end of iter ≈ 1 full
//   warp-iteration ≈ 300 wall-cycles in flight ≥ L2 latency).
// ---------------------------------------------------------------------------
#define JSMEM 65536                 // A only

__device__ __forceinline__ void run_vt40(
    uint32_t sbA, const uint2* __restrict__ wbase,
    const float* __restrict__ bout, float* __restrict__ outbt,
    int vtn0, int rowA, uint32_t swz, int khA, int l)
{
    const int NF = 5;
    int gr = l >> 2, ct = l & 3;
    float acc[4][NF][4];
    #pragma unroll
    for (int nf = 0; nf < NF; nf++) {
        int cc = vtn0 + nf * 8 + 2 * ct;
        float b0 = __ldg(&bout[cc]), b1 = __ldg(&bout[cc + 1]);
        #pragma unroll
        for (int mf = 0; mf < 4; mf++) {
            acc[mf][nf][0] = b0; acc[mf][nf][1] = b1;
            acc[mf][nf][2] = b0; acc[mf][nf][3] = b1;
        }
    }

    // B ping-pong: slot ks&1 holds B(ks); refilled for ks+2 after use.
    uint2 bf[2][NF];
    #pragma unroll
    for (int nb = 0; nb < NF; nb++) {
        bf[0][nb] = __ldg(wbase + nb * 1024);
        bf[1][nb] = __ldg(wbase + nb * 1024 + 32);
    }

    #pragma unroll
    for (int ks = 0; ks < 32; ks++) {
        const int cur = ks & 1;
        uint32_t bc = (uint32_t)(ks * 32 + khA) ^ swz;
        uint32_t a[2][4];
        #pragma unroll
        for (int mf = 0; mf < 2; mf++)
            ldmx4(a[mf], sbA + (uint32_t)(mf * 16 + rowA) * 1024 + bc);
        #pragma unroll
        for (int mf = 0; mf < 2; mf++)
            #pragma unroll
            for (int nf = 0; nf < NF; nf++)
                mma16816(acc[mf][nf], a[mf], bf[cur][nf].x, bf[cur][nf].y);
        #pragma unroll
        for (int mf = 0; mf < 2; mf++)
            ldmx4(a[mf], sbA + (uint32_t)((mf + 2) * 16 + rowA) * 1024 + bc);
        #pragma unroll
        for (int mf = 0; mf < 2; mf++)
            #pragma unroll
            for (int nf = 0; nf < NF; nf++)
                mma16816(acc[mf + 2][nf], a[mf], bf[cur][nf].x, bf[cur][nf].y);
        if (ks + 2 < 32) {
            #pragma unroll
            for (int nb = 0; nb < NF; nb++)
                bf[cur][nb] = __ldg(wbase + nb * 1024 + (ks + 2) * 32);
        }
    }

    // Epilogue (bias already folded in).
    #pragma unroll
    for (int nf = 0; nf < NF; nf++) {
        int cc = vtn0 + nf * 8 + 2 * ct;
        #pragma unroll
        for (int mf = 0; mf < 4; mf++) {
            int u = mf * 16 + gr;
            float* p = outbt + (size_t)u * Vc + cc;
            float2 t0; t0.x = acc[mf][nf][0]; t0.y = acc[mf][nf][1];
            float2 t1; t1.x = acc[mf][nf][2]; t1.y = acc[mf][nf][3];
            *(float2*)p = t0;
            *(float2*)(p + 8 * Vc) = t1;
        }
    }
}

__global__ __launch_bounds__(256, 2) void joint_kernel(
    const float* __restrict__ bout, float* __restrict__ out)
{
    extern __shared__ char smem[];
    uint32_t sbA = smem_u32(smem);
    int tid = threadIdx.x, l = tid & 31, w = tid >> 5;
    int bx = blockIdx.x;
    int bt = bx >> 1, uh = bx & 1;
    int b = bt >> 8;
    const float* encR = g_enc + (size_t)bt * Hc;
    const float* decB = g_dec + ((size_t)b * Uc + uh * 64) * Hc;

    // Fill A[64][512]: rows have 1024B stride, SW128-style XOR swizzle.
    #pragma unroll
    for (int i = 0; i < 16; i++) {
        int idx = i * 256 + tid;          // 4096 units of 8 halfs
        int r = idx >> 6, cg = idx & 63;
        int kc = cg * 8;
        float4 d0 = *(const float4*)(decB + (size_t)r * Hc + kc);
        float4 d1 = *(const float4*)(decB + (size_t)r * Hc + kc + 4);
        float4 e0 = *(const float4*)(encR + kc);
        float4 e1 = *(const float4*)(encR + kc + 4);
        uint4 q;
        q.x = pack2(tanh_fast(d0.x + e0.x), tanh_fast(d0.y + e0.y));
        q.y = pack2(tanh_fast(d0.z + e0.z), tanh_fast(d0.w + e0.w));
        q.z = pack2(tanh_fast(d1.x + e1.x), tanh_fast(d1.y + e1.y));
        q.w = pack2(tanh_fast(d1.z + e1.z), tanh_fast(d1.w + e1.w));
        uint32_t off = (uint32_t)r * 1024 + (((uint32_t)cg * 16) ^ (((uint32_t)r & 7) << 4));
        asm volatile("st.shared.v4.b32 [%0], {%1,%2,%3,%4};"
                     :: "r"(sbA + off), "r"(q.x), "r"(q.y), "r"(q.z), "r"(q.w)
                     : "memory");
    }
    __syncthreads();   // the ONLY barrier

    int rowA = l & 15, khA = (l >> 4) * 16;
    uint32_t swz = ((uint32_t)l & 7) << 4;
    float* outbt = out + ((size_t)bt * Uc + uh * 64) * Vc;

    // Each warp: contiguous 80 v-columns, two passes of 40.
    {
        int n0 = w * 80;
        const uint2* wb = g_Wf + (size_t)(n0 >> 3) * 1024 + l;
        run_vt40(sbA, wb, bout, outbt, n0, rowA, swz, khA, l);
    }
    {
        int n0 = w * 80 + 40;
        const uint2* wb = g_Wf + (size_t)(n0 >> 3) * 1024 + l;
        run_vt40(sbA, wb, bout, outbt, n0, rowA, swz, khA, l);
    }
}

// ---------------------------------------------------------------------------
extern "C" void kernel_launch(void* const* d_in, const int* in_sizes, int n_in,
                              void* d_out, int out_size)
{
    const float* enc_out = (const float*)d_in[0];
    const float* dec_out = (const float*)d_in[1];
    const float* W_enc   = (const float*)d_in[2];
    const float* b_enc   = (const float*)d_in[3];
    const float* W_dec   = (const float*)d_in[4];
    const float* W_out   = (const float*)d_in[5];
    const float* b_out   = (const float*)d_in[6];
    float* out = (float*)d_out;

    cudaFuncSetAttribute(joint_kernel,
                         cudaFuncAttributeMaxDynamicSharedMemorySize, JSMEM);

    prep_kernel<<<dim3(8, 16, 3), 256>>>(enc_out, dec_out, W_enc, b_enc, W_dec, W_out);
    joint_kernel<<<2 * Bc * Tc, 256, JSMEM>>>(b_out, out);
}